// round 9
// baseline (speedup 1.0000x reference)
#include <cuda_runtime.h>

namespace {

constexpr int D    = 16;
constexpr int KNN  = 16;
constexpr int GS   = 10;            // grid cells per axis
constexpr int NC   = GS * GS * GS;  // 1000 cells
constexpr int ACAP = 96;            // atoms per cell capacity (mean ~20)
constexpr int QCAP = 320;           // queries per cell capacity (mean ~82)
constexpr int NMAX = 81920;
constexpr int KBLK = 64;            // kNN block size
constexpr int SSTAGE = 768;         // staged atoms capacity (mean 540)
constexpr int BCAP = 72;            // per-thread survivor buffer (u64 keys)
constexpr float CSEL = 40.0f;       // target accepted-candidate count

typedef unsigned long long u64;

} // namespace

// ---- scratch (no allocs allowed) ----
__device__ int    g_acnt[NC];
__device__ int    g_qcnt[NC];
__device__ float4 g_atoms[NC * ACAP];   // xyz + orig idx bits in .w
__device__ int    g_qidx[NC * QCAP];
__device__ int    g_bbenc[6] = {0x7fffffff, 0x7fffffff, 0x7fffffff,
                                (int)0x80000000, (int)0x80000000, (int)0x80000000};
__device__ float  g_org[3], g_h[3], g_hinv[3];
__device__ float  g_ndist[NMAX * KNN];
__device__ int    g_nidx[NMAX * KNN];

namespace {

__device__ const signed char NBR[27][3] = {
    {0,0,0},
    {-1,0,0},{1,0,0},{0,-1,0},{0,1,0},{0,0,-1},{0,0,1},
    {-1,-1,0},{-1,1,0},{1,-1,0},{1,1,0},
    {-1,0,-1},{-1,0,1},{1,0,-1},{1,0,1},
    {0,-1,-1},{0,-1,1},{0,1,-1},{0,1,1},
    {-1,-1,-1},{-1,-1,1},{-1,1,-1},{-1,1,1},
    {1,-1,-1},{1,-1,1},{1,1,-1},{1,1,1}
};

__device__ __forceinline__ int fenc(float f) {
    int b = __float_as_int(f);
    return (b < 0) ? (b ^ 0x7fffffff) : b;
}
__device__ __forceinline__ float fdec(int b) {
    return __int_as_float((b < 0) ? (b ^ 0x7fffffff) : b);
}
__device__ __forceinline__ u64 pack_key(float d, unsigned idxbits) {
    return ((u64)__float_as_uint(d) << 32) | (u64)idxbits;
}

__global__ void k_bbox(const float* __restrict__ y, int M) {
    int i = blockIdx.x * blockDim.x + threadIdx.x;
    bool v = i < M;
    float mn[3], mx[3];
    const float INF = __int_as_float(0x7f800000);
#pragma unroll
    for (int a = 0; a < 3; ++a) {
        float p = v ? y[3 * i + a] : 0.f;
        mn[a] = v ? p : INF;
        mx[a] = v ? p : -INF;
    }
#pragma unroll
    for (int o = 16; o; o >>= 1) {
#pragma unroll
        for (int a = 0; a < 3; ++a) {
            mn[a] = fminf(mn[a], __shfl_down_sync(0xffffffffu, mn[a], o));
            mx[a] = fmaxf(mx[a], __shfl_down_sync(0xffffffffu, mx[a], o));
        }
    }
    if ((threadIdx.x & 31) == 0) {
#pragma unroll
        for (int a = 0; a < 3; ++a) {
            atomicMin(&g_bbenc[a],     fenc(mn[a]));
            atomicMax(&g_bbenc[3 + a], fenc(mx[a]));
        }
    }
}

__global__ void k_params() {
#pragma unroll
    for (int a = 0; a < 3; ++a) {
        float mn = fdec(g_bbenc[a]);
        float mx = fdec(g_bbenc[3 + a]);
        float ext = fmaxf(mx - mn, 1e-6f);
        g_org[a]  = mn;
        g_h[a]    = ext / GS;
        g_hinv[a] = GS / ext;
    }
}

__device__ __forceinline__ int cell_of(float p, int a) {
    int c = (int)((p - g_org[a]) * g_hinv[a]);
    return min(GS - 1, max(0, c));
}

__global__ void k_bin(const float* __restrict__ x, const float* __restrict__ y,
                      int N, int M) {
    int i = blockIdx.x * blockDim.x + threadIdx.x;
    if (i < M) {
        float ax = y[3 * i], ay = y[3 * i + 1], az = y[3 * i + 2];
        int c = (cell_of(az, 2) * GS + cell_of(ay, 1)) * GS + cell_of(ax, 0);
        int slot = atomicAdd(&g_acnt[c], 1);
        if (slot < ACAP)
            g_atoms[c * ACAP + slot] = make_float4(ax, ay, az, __int_as_float(i));
    }
    if (i < N) {
        int c = (cell_of(x[3 * i + 2], 2) * GS + cell_of(x[3 * i + 1], 1)) * GS
              + cell_of(x[3 * i], 0);
        int slot = atomicAdd(&g_qcnt[c], 1);
        if (slot < QCAP) g_qidx[c * QCAP + slot] = i;
    }
}

// ---- kNN: 2 blocks per cell; staged smem; BRANCHLESS threshold filter with
//      packed u64 keys; insertion only over ~40 survivors ----
__global__ __launch_bounds__(KBLK)
void k_knn(const float* __restrict__ x)
{
    __shared__ float4 satoms[SSTAGE];
    __shared__ int soff[28];
    __shared__ int s_cnt[27];
    __shared__ int s_gbase[27];
    __shared__ unsigned char s_ok[27];
    __shared__ float sT;

    const int tid  = threadIdx.x;
    const int cell = blockIdx.x >> 1;
    const int half = blockIdx.x & 1;

    const int cx0 = cell % GS;
    const int cy0 = (cell / GS) % GS;
    const int cz0 = cell / (GS * GS);

    const float ox = g_org[0], oy = g_org[1], oz = g_org[2];
    const float hx = g_h[0],   hy = g_h[1],   hz = g_h[2];

    if (tid < 27) {
        int cx = cx0 + NBR[tid][0];
        int cy = cy0 + NBR[tid][1];
        int cz = cz0 + NBR[tid][2];
        bool ok = (cx >= 0) & (cx < GS) & (cy >= 0) & (cy < GS) &
                  (cz >= 0) & (cz < GS);
        int c = ok ? ((cz * GS + cy) * GS + cx) : 0;
        s_cnt[tid]   = ok ? min(g_acnt[c], ACAP) : 0;
        s_gbase[tid] = c * ACAP;
        s_ok[tid]    = ok ? 1 : 0;
    }
    __syncthreads();
    if (tid == 0) {
        int acc = 0;
        int navail = 0;
#pragma unroll
        for (int j = 0; j < 27; ++j) {
            soff[j] = acc;
            acc += s_cnt[j];
            navail += s_ok[j];
        }
        soff[27] = acc;
        float vol = (float)navail * hx * hy * hz;
        float tt  = (acc > 0) ? (3.f * CSEL * vol) / (12.5663706f * (float)acc)
                              : 1e30f;
        sT = cbrtf(tt * tt);          // r^2 with E[accepted] ~= CSEL
    }
    __syncthreads();

    const bool use_smem = soff[27] <= SSTAGE;
    if (use_smem) {
#pragma unroll 1
        for (int j = 0; j < 27; ++j) {
            const int n = s_cnt[j], o = soff[j], gb = s_gbase[j];
            for (int i = tid; i < n; i += KBLK)
                satoms[o + i] = g_atoms[gb + i];
        }
    }
    __syncthreads();

    const int nq  = min(g_qcnt[cell], QCAP);
    const int mid = (nq + 1) >> 1;
    const int lo  = half ? mid : 0;
    const int hi  = half ? nq  : mid;
    const float INF = __int_as_float(0x7f800000);
    const u64 KSENT = 0x7F800000FFFFFFFFull;   // (INF, idx=0xFFFFFFFF)

    for (int t0 = lo; t0 < hi; t0 += KBLK) {
        const int  t      = t0 + tid;
        const bool active = t < hi;
        const int  qi     = g_qidx[cell * QCAP + (active ? t : lo)];
        const float px = x[3 * qi], py = x[3 * qi + 1], pz = x[3 * qi + 2];

        u64 key[KNN];
#pragma unroll
        for (int j = 0; j < KNN; ++j) key[j] = KSENT;
        u64 worstk = active ? KSENT : 0ull;

        auto insertk = [&](u64 k) {
            key[KNN - 1] = k;
#pragma unroll
            for (int j = KNN - 1; j > 0; --j) {
                if (key[j] < key[j - 1]) {
                    u64 tk = key[j]; key[j] = key[j - 1]; key[j - 1] = tk;
                }
            }
            worstk = key[KNN - 1];
        };
        auto worstd = [&]() -> float {
            return __uint_as_float((unsigned)(worstk >> 32));
        };

        if (use_smem) {
            // ---- phase 1: BRANCHLESS filter (unconditional store, predicated advance) ----
            const float T = active ? sT : -1.f;
            const int total = soff[27];
            u64 kbuf[BCAP];
            int cnt = 0;

            int i = 0;
#pragma unroll 1
            for (; i + 4 <= total; i += 4) {
                float4 q0 = satoms[i + 0], q1 = satoms[i + 1];
                float4 q2 = satoms[i + 2], q3 = satoms[i + 3];
                float dx0 = px - q0.x, dy0 = py - q0.y, dz0 = pz - q0.z;
                float dx1 = px - q1.x, dy1 = py - q1.y, dz1 = pz - q1.z;
                float dx2 = px - q2.x, dy2 = py - q2.y, dz2 = pz - q2.z;
                float dx3 = px - q3.x, dy3 = py - q3.y, dz3 = pz - q3.z;
                float d0 = fmaf(dx0, dx0, fmaf(dy0, dy0, dz0 * dz0));
                float d1 = fmaf(dx1, dx1, fmaf(dy1, dy1, dz1 * dz1));
                float d2 = fmaf(dx2, dx2, fmaf(dy2, dy2, dz2 * dz2));
                float d3 = fmaf(dx3, dx3, fmaf(dy3, dy3, dz3 * dz3));
                int c0 = min(cnt, BCAP - 1);
                kbuf[c0] = pack_key(d0, __float_as_uint(q0.w));
                cnt += (d0 < T);
                int c1 = min(cnt, BCAP - 1);
                kbuf[c1] = pack_key(d1, __float_as_uint(q1.w));
                cnt += (d1 < T);
                int c2 = min(cnt, BCAP - 1);
                kbuf[c2] = pack_key(d2, __float_as_uint(q2.w));
                cnt += (d2 < T);
                int c3 = min(cnt, BCAP - 1);
                kbuf[c3] = pack_key(d3, __float_as_uint(q3.w));
                cnt += (d3 < T);
            }
#pragma unroll 1
            for (; i < total; ++i) {
                float4 q = satoms[i];
                float dx = px - q.x, dy = py - q.y, dz = pz - q.z;
                float d = fmaf(dx, dx, fmaf(dy, dy, dz * dz));
                int c = min(cnt, BCAP - 1);
                kbuf[c] = pack_key(d, __float_as_uint(q.w));
                cnt += (d < T);
            }

            const bool fb = active && (cnt < KNN || cnt > BCAP);

            // ---- phase 2: insertion over survivors only ----
            if (active && !fb) {
#pragma unroll 1
                for (int j = 0; j < cnt; ++j) {
                    u64 k = kbuf[j];
                    if (k < worstk) insertk(k);
                }
            }

            // ---- rare exact fallback: full insert-scan of the staged set ----
            if (__any_sync(0xffffffffu, fb)) {
                if (fb) {
#pragma unroll 1
                    for (int j = 0; j < total; ++j) {
                        float4 q = satoms[j];
                        float dx = px - q.x, dy = py - q.y, dz = pz - q.z;
                        float d = fmaf(dx, dx, fmaf(dy, dy, dz * dz));
                        u64 k = pack_key(d, __float_as_uint(q.w));
                        if (k < worstk) insertk(k);
                    }
                }
            }
        } else if (active) {
            // staging overflow (essentially impossible): gmem insert scan
#pragma unroll 1
            for (int j = 0; j < 27; ++j) {
                const int na = s_cnt[j];
                const float4* __restrict__ ap = &g_atoms[s_gbase[j]];
#pragma unroll 1
                for (int i = 0; i < na; ++i) {
                    float4 q = ap[i];
                    float dx = px - q.x, dy = py - q.y, dz = pz - q.z;
                    float d = fmaf(dx, dx, fmaf(dy, dy, dz * dz));
                    u64 k = pack_key(d, __float_as_uint(q.w));
                    if (k < worstk) insertk(k);
                }
            }
        }

        // ---- guarantee check + rare shell expansion ----
        {
            int R = 1;
            while (true) {
                float g = INF;
                if (cx0 - R > 0)      g = fminf(g, px - (ox + (cx0 - R) * hx));
                if (cx0 + R < GS - 1) g = fminf(g, (ox + (cx0 + R + 1) * hx) - px);
                if (cy0 - R > 0)      g = fminf(g, py - (oy + (cy0 - R) * hy));
                if (cy0 + R < GS - 1) g = fminf(g, (oy + (cy0 + R + 1) * hy) - py);
                if (cz0 - R > 0)      g = fminf(g, pz - (oz + (cz0 - R) * hz));
                if (cz0 + R < GS - 1) g = fminf(g, (oz + (cz0 + R + 1) * hz) - pz);
                g = g - 1e-4f;
                if (worstd() <= g * g) break;
                ++R;
                const int zlo = max(cz0 - R, 0), zhi = min(cz0 + R, GS - 1);
                const int ylo = max(cy0 - R, 0), yhi = min(cy0 + R, GS - 1);
                const int xlo = max(cx0 - R, 0), xhi = min(cx0 + R, GS - 1);
                for (int cz = zlo; cz <= zhi; ++cz)
                    for (int cy = ylo; cy <= yhi; ++cy)
                        for (int cx = xlo; cx <= xhi; ++cx) {
                            int ch = max(abs(cx - cx0), max(abs(cy - cy0), abs(cz - cz0)));
                            if (ch != R) continue;
                            int c = (cz * GS + cy) * GS + cx;
                            float bx0 = ox + cx * hx, by0 = oy + cy * hy, bz0 = oz + cz * hz;
                            float tx = fmaxf(0.f, fmaxf(bx0 - px, px - (bx0 + hx)));
                            float ty = fmaxf(0.f, fmaxf(by0 - py, py - (by0 + hy)));
                            float tz = fmaxf(0.f, fmaxf(bz0 - pz, pz - (bz0 + hz)));
                            float mind = fmaf(tx, tx, fmaf(ty, ty, tz * tz));
                            if (mind < worstd()) {
                                int na = min(g_acnt[c], ACAP);
                                const float4* __restrict__ ap = &g_atoms[c * ACAP];
#pragma unroll 1
                                for (int i = 0; i < na; ++i) {
                                    float4 q = ap[i];
                                    float dx = px - q.x, dy = py - q.y, dz = pz - q.z;
                                    float d = fmaf(dx, dx, fmaf(dy, dy, dz * dz));
                                    u64 k = pack_key(d, __float_as_uint(q.w));
                                    if (k < worstk) insertk(k);
                                }
                            }
                        }
            }
        }

        if (active) {
            float dist[KNN];
            int   idx[KNN];
#pragma unroll
            for (int j = 0; j < KNN; ++j) {
                dist[j] = __uint_as_float((unsigned)(key[j] >> 32));
                idx[j]  = (int)(unsigned)(key[j] & 0xFFFFFFFFull);
            }
            float4* dp = reinterpret_cast<float4*>(g_ndist + (size_t)qi * KNN);
            int4*   ip = reinterpret_cast<int4*>(g_nidx + (size_t)qi * KNN);
            dp[0] = make_float4(dist[0],  dist[1],  dist[2],  dist[3]);
            dp[1] = make_float4(dist[4],  dist[5],  dist[6],  dist[7]);
            dp[2] = make_float4(dist[8],  dist[9],  dist[10], dist[11]);
            dp[3] = make_float4(dist[12], dist[13], dist[14], dist[15]);
            ip[0] = make_int4(idx[0],  idx[1],  idx[2],  idx[3]);
            ip[1] = make_int4(idx[4],  idx[5],  idx[6],  idx[7]);
            ip[2] = make_int4(idx[8],  idx[9],  idx[10], idx[11]);
            ip[3] = make_int4(idx[12], idx[13], idx[14], idx[15]);
        }
    }
}

// ---- MLP over the K neighbors ----
__global__ __launch_bounds__(128)
void k_mlp(const float* __restrict__ atype,
           const float* __restrict__ W1, const float* __restrict__ b1,
           const float* __restrict__ W2, const float* __restrict__ b2,
           const float* __restrict__ W3, const float* __restrict__ b3,
           const float* __restrict__ bn1g, const float* __restrict__ bn1b,
           const float* __restrict__ bn1m, const float* __restrict__ bn1v,
           const float* __restrict__ bn2g, const float* __restrict__ bn2b,
           const float* __restrict__ bn2m, const float* __restrict__ bn2v,
           float* __restrict__ out, int N)
{
    __shared__ float sW1[(D + 1) * D];
    __shared__ float sW2[D * D];
    __shared__ float sW3[2 * D * D];
    __shared__ float sb1[D], sb2[D], sb3[D];
    __shared__ float ss1[D], st1[D], ss2[D], st2[D];

    const int tid = threadIdx.x;
    for (int i = tid; i < (D + 1) * D; i += 128) sW1[i] = W1[i];
    for (int i = tid; i < D * D;       i += 128) sW2[i] = W2[i];
    for (int i = tid; i < 2 * D * D;   i += 128) sW3[i] = W3[i];
    if (tid < D) {
        sb1[tid] = b1[tid];
        sb2[tid] = b2[tid];
        sb3[tid] = b3[tid];
        float s1 = bn1g[tid] * rsqrtf(bn1v[tid] + 1e-5f);
        ss1[tid] = s1;
        st1[tid] = fmaf(-bn1m[tid], s1, bn1b[tid]);
        float s2 = bn2g[tid] * rsqrtf(bn2v[tid] + 1e-5f);
        ss2[tid] = s2;
        st2[tid] = fmaf(-bn2m[tid], s2, bn2b[tid]);
    }
    __syncthreads();

    const int n = blockIdx.x * 128 + tid;
    if (n >= N) return;

    const float4* dp = reinterpret_cast<const float4*>(g_ndist + (size_t)n * KNN);
    const int4*   ip = reinterpret_cast<const int4*>(g_nidx + (size_t)n * KNN);
    float4 dv[4] = {dp[0], dp[1], dp[2], dp[3]};
    int4   iv[4] = {ip[0], ip[1], ip[2], ip[3]};
    const float* dists = reinterpret_cast<const float*>(dv);
    const int*   idxs  = reinterpret_cast<const int*>(iv);

    float fx1[D], fx2[D];
#pragma unroll
    for (int d = 0; d < D; ++d) { fx1[d] = 0.f; fx2[d] = 0.f; }

#pragma unroll 1
    for (int k = 0; k < KNN; ++k) {
        const int   j  = idxs[k];
        const float dk = dists[k];

        const float4* ap = reinterpret_cast<const float4*>(atype + (size_t)j * D);
        float4 a0 = ap[0], a1 = ap[1], a2 = ap[2], a3 = ap[3];
        float f[D + 1] = {a0.x, a0.y, a0.z, a0.w,
                          a1.x, a1.y, a1.z, a1.w,
                          a2.x, a2.y, a2.z, a2.w,
                          a3.x, a3.y, a3.z, a3.w,
                          1.0f / dk};

        float h[D];
#pragma unroll
        for (int d = 0; d < D; ++d) h[d] = sb1[d];
#pragma unroll
        for (int s = 0; s < D + 1; ++s) {
            const float ft = f[s];
#pragma unroll
            for (int d = 0; d < D; ++d) h[d] = fmaf(ft, sW1[s * D + d], h[d]);
        }
#pragma unroll
        for (int d = 0; d < D; ++d) {
            float v = h[d];
            v = (v > 0.f) ? v : 0.2f * v;
            v = fmaf(v, ss1[d], st1[d]);
            h[d] = v;
            fx1[d] += v;
        }

        float h2[D];
#pragma unroll
        for (int d = 0; d < D; ++d) h2[d] = sb2[d];
#pragma unroll
        for (int s = 0; s < D; ++s) {
            const float ht = h[s];
#pragma unroll
            for (int d = 0; d < D; ++d) h2[d] = fmaf(ht, sW2[s * D + d], h2[d]);
        }
#pragma unroll
        for (int d = 0; d < D; ++d) {
            float v = h2[d];
            v = (v > 0.f) ? v : 0.2f * v;
            fx2[d] += fmaf(v, ss2[d], st2[d]);
        }
    }

    float o[D];
#pragma unroll
    for (int d = 0; d < D; ++d) o[d] = sb3[d];
#pragma unroll
    for (int s = 0; s < D; ++s) {
        const float a = fx1[s];
#pragma unroll
        for (int d = 0; d < D; ++d) o[d] = fmaf(a, sW3[s * D + d], o[d]);
    }
#pragma unroll
    for (int s = 0; s < D; ++s) {
        const float a = fx2[s];
#pragma unroll
        for (int d = 0; d < D; ++d) o[d] = fmaf(a, sW3[(D + s) * D + d], o[d]);
    }

    float4* op = reinterpret_cast<float4*>(out + (size_t)n * D);
    op[0] = make_float4(o[0],  o[1],  o[2],  o[3]);
    op[1] = make_float4(o[4],  o[5],  o[6],  o[7]);
    op[2] = make_float4(o[8],  o[9],  o[10], o[11]);
    op[3] = make_float4(o[12], o[13], o[14], o[15]);
}

__global__ void k_reset() {   // restore counters for the next graph replay
    int i = blockIdx.x * blockDim.x + threadIdx.x;
    if (i < NC) { g_acnt[i] = 0; g_qcnt[i] = 0; }
    if (i < 3)           g_bbenc[i] = 0x7fffffff;
    if (i >= 3 && i < 6) g_bbenc[i] = (int)0x80000000;
}

} // namespace

extern "C" void kernel_launch(void* const* d_in, const int* in_sizes, int n_in,
                              void* d_out, int out_size)
{
    const float* x     = (const float*)d_in[0];
    const float* y     = (const float*)d_in[1];
    const float* atype = (const float*)d_in[2];
    const float* W1    = (const float*)d_in[5];
    const float* b1    = (const float*)d_in[6];
    const float* W2    = (const float*)d_in[7];
    const float* b2    = (const float*)d_in[8];
    const float* W3    = (const float*)d_in[9];
    const float* b3    = (const float*)d_in[10];
    const float* bn1g  = (const float*)d_in[11];
    const float* bn1b  = (const float*)d_in[12];
    const float* bn1m  = (const float*)d_in[13];
    const float* bn1v  = (const float*)d_in[14];
    const float* bn2g  = (const float*)d_in[15];
    const float* bn2b  = (const float*)d_in[16];
    const float* bn2m  = (const float*)d_in[17];
    const float* bn2v  = (const float*)d_in[18];

    const int N = in_sizes[0] / 3;
    const int M = in_sizes[1] / 3;
    const int NM = (N > M) ? N : M;

    // launch order chosen so the profiler's capture window (4th launch) hits k_knn
    k_bbox<<<(M + 255) / 256, 256>>>(y, M);
    k_params<<<1, 1>>>();
    k_bin<<<(NM + 255) / 256, 256>>>(x, y, N, M);
    k_knn<<<NC * 2, KBLK>>>(x);
    k_mlp<<<(N + 127) / 128, 128>>>(atype,
                                    W1, b1, W2, b2, W3, b3,
                                    bn1g, bn1b, bn1m, bn1v,
                                    bn2g, bn2b, bn2m, bn2v,
                                    (float*)d_out, N);
    k_reset<<<(NC + 255) / 256, 256>>>();
}

// round 10
// speedup vs baseline: 1.4710x; 1.4710x over previous
#include <cuda_runtime.h>

namespace {

constexpr int D    = 16;
constexpr int KNN  = 16;
constexpr int GS   = 10;            // grid cells per axis
constexpr int NC   = GS * GS * GS;  // 1000 cells
constexpr int ACAP = 96;            // atoms per cell capacity (mean ~20)
constexpr int QCAP = 320;           // queries per cell capacity (mean ~82)
constexpr int NMAX = 81920;
constexpr int KBLK = 128;           // kNN block size (4 warps)
constexpr int SSTAGE = 768;         // staged atoms capacity (mean 540)
constexpr int BCAP = 80;            // per-thread threshold buffer capacity
constexpr float CSEL = 40.0f;       // target accepted-candidate count

} // namespace

// ---- scratch (no allocs allowed; zero-initialized at load) ----
__device__ int    g_acnt[NC];
__device__ int    g_qcnt[NC];
__device__ float4 g_atoms[NC * ACAP];   // xyz + orig idx bits in .w
__device__ int    g_qidx[NC * QCAP];
__device__ int    g_bbenc[6] = {0x7fffffff, 0x7fffffff, 0x7fffffff,
                                (int)0x80000000, (int)0x80000000, (int)0x80000000};
__device__ float  g_org[3], g_h[3], g_hinv[3];
__device__ float  g_ndist[NMAX * KNN];
__device__ int    g_nidx[NMAX * KNN];

namespace {

__device__ const signed char NBR[27][3] = {
    {0,0,0},
    {-1,0,0},{1,0,0},{0,-1,0},{0,1,0},{0,0,-1},{0,0,1},
    {-1,-1,0},{-1,1,0},{1,-1,0},{1,1,0},
    {-1,0,-1},{-1,0,1},{1,0,-1},{1,0,1},
    {0,-1,-1},{0,-1,1},{0,1,-1},{0,1,1},
    {-1,-1,-1},{-1,-1,1},{-1,1,-1},{-1,1,1},
    {1,-1,-1},{1,-1,1},{1,1,-1},{1,1,1}
};

__device__ __forceinline__ int fenc(float f) {
    int b = __float_as_int(f);
    return (b < 0) ? (b ^ 0x7fffffff) : b;
}
__device__ __forceinline__ float fdec(int b) {
    return __int_as_float((b < 0) ? (b ^ 0x7fffffff) : b);
}

__global__ void k_bbox(const float* __restrict__ y, int M) {
    int i = blockIdx.x * blockDim.x + threadIdx.x;
    bool v = i < M;
    float mn[3], mx[3];
    const float INF = __int_as_float(0x7f800000);
#pragma unroll
    for (int a = 0; a < 3; ++a) {
        float p = v ? y[3 * i + a] : 0.f;
        mn[a] = v ? p : INF;
        mx[a] = v ? p : -INF;
    }
#pragma unroll
    for (int o = 16; o; o >>= 1) {
#pragma unroll
        for (int a = 0; a < 3; ++a) {
            mn[a] = fminf(mn[a], __shfl_down_sync(0xffffffffu, mn[a], o));
            mx[a] = fmaxf(mx[a], __shfl_down_sync(0xffffffffu, mx[a], o));
        }
    }
    if ((threadIdx.x & 31) == 0) {
#pragma unroll
        for (int a = 0; a < 3; ++a) {
            atomicMin(&g_bbenc[a],     fenc(mn[a]));
            atomicMax(&g_bbenc[3 + a], fenc(mx[a]));
        }
    }
}

__global__ void k_params() {
#pragma unroll
    for (int a = 0; a < 3; ++a) {
        float mn = fdec(g_bbenc[a]);
        float mx = fdec(g_bbenc[3 + a]);
        float ext = fmaxf(mx - mn, 1e-6f);
        g_org[a]  = mn;
        g_h[a]    = ext / GS;
        g_hinv[a] = GS / ext;
    }
}

__device__ __forceinline__ int cell_of(float p, int a) {
    int c = (int)((p - g_org[a]) * g_hinv[a]);
    return min(GS - 1, max(0, c));
}

__global__ void k_bin(const float* __restrict__ x, const float* __restrict__ y,
                      int N, int M) {
    int i = blockIdx.x * blockDim.x + threadIdx.x;
    if (i < M) {
        float ax = y[3 * i], ay = y[3 * i + 1], az = y[3 * i + 2];
        int c = (cell_of(az, 2) * GS + cell_of(ay, 1)) * GS + cell_of(ax, 0);
        int slot = atomicAdd(&g_acnt[c], 1);
        if (slot < ACAP)
            g_atoms[c * ACAP + slot] = make_float4(ax, ay, az, __int_as_float(i));
    }
    if (i < N) {
        int c = (cell_of(x[3 * i + 2], 2) * GS + cell_of(x[3 * i + 1], 1)) * GS
              + cell_of(x[3 * i], 0);
        int slot = atomicAdd(&g_qcnt[c], 1);
        if (slot < QCAP) g_qidx[c * QCAP + slot] = i;
    }
}

// ---- kNN: 1 block per cell (4 warps); staged smem neighborhood; threshold
//      filter + deferred selection. launch_bounds pins regs for 50% occupancy ----
__global__ __launch_bounds__(KBLK, 8)
void k_knn(const float* __restrict__ x)
{
    __shared__ float4 satoms[SSTAGE];
    __shared__ int soff[28];
    __shared__ int s_cnt[27];
    __shared__ int s_gbase[27];
    __shared__ unsigned char s_ok[27];
    __shared__ float sT;

    const int tid  = threadIdx.x;
    const int cell = blockIdx.x;

    const int cx0 = cell % GS;
    const int cy0 = (cell / GS) % GS;
    const int cz0 = cell / (GS * GS);

    const float ox = g_org[0], oy = g_org[1], oz = g_org[2];
    const float hx = g_h[0],   hy = g_h[1],   hz = g_h[2];

    if (tid < 27) {
        int cx = cx0 + NBR[tid][0];
        int cy = cy0 + NBR[tid][1];
        int cz = cz0 + NBR[tid][2];
        bool ok = (cx >= 0) & (cx < GS) & (cy >= 0) & (cy < GS) &
                  (cz >= 0) & (cz < GS);
        int c = ok ? ((cz * GS + cy) * GS + cx) : 0;
        s_cnt[tid]   = ok ? min(g_acnt[c], ACAP) : 0;
        s_gbase[tid] = c * ACAP;
        s_ok[tid]    = ok ? 1 : 0;
    }
    __syncthreads();
    if (tid == 0) {
        int acc = 0;
        int navail = 0;
#pragma unroll
        for (int j = 0; j < 27; ++j) {
            soff[j] = acc;
            acc += s_cnt[j];
            navail += s_ok[j];
        }
        soff[27] = acc;
        // density-derived threshold: E[accepted] ~= CSEL
        float vol = (float)navail * hx * hy * hz;
        float tt  = (acc > 0) ? (3.f * CSEL * vol) / (12.5663706f * (float)acc)
                              : 1e30f;
        sT = cbrtf(tt * tt);          // (r^3)^(2/3) = r^2
    }
    __syncthreads();

    const bool use_smem = soff[27] <= SSTAGE;
    if (use_smem) {
#pragma unroll 1
        for (int j = 0; j < 27; ++j) {
            const int n = s_cnt[j], o = soff[j], gb = s_gbase[j];
            for (int i = tid; i < n; i += KBLK)
                satoms[o + i] = g_atoms[gb + i];
        }
    }
    __syncthreads();

    const int nq = min(g_qcnt[cell], QCAP);
    const float INF = __int_as_float(0x7f800000);

    for (int t0 = 0; t0 < nq; t0 += KBLK) {
        const int  t      = t0 + tid;
        const bool active = t < nq;
        const int  qi     = g_qidx[cell * QCAP + (active ? t : 0)];
        const float px = x[3 * qi], py = x[3 * qi + 1], pz = x[3 * qi + 2];

        float dist[KNN];
        int   idx[KNN];
#pragma unroll
        for (int j = 0; j < KNN; ++j) { dist[j] = INF; idx[j] = 0; }
        float worst = active ? INF : 0.f;

        auto insert = [&](float d, int gi) {
            dist[KNN - 1] = d;
            idx[KNN - 1]  = gi;
#pragma unroll
            for (int j = KNN - 1; j > 0; --j) {
                if (dist[j] < dist[j - 1]) {
                    float td = dist[j]; dist[j] = dist[j - 1]; dist[j - 1] = td;
                    int   ti = idx[j];  idx[j]  = idx[j - 1];  idx[j - 1]  = ti;
                }
            }
            worst = dist[KNN - 1];
        };

        if (use_smem) {
            // ---- phase 1: flat threshold filter over the staged set ----
            const float T = active ? sT : -1.f;
            const int total = soff[27];
            float fbuf[BCAP];
            int   ibuf[BCAP];
            int   cnt = 0;

            int i = 0;
#pragma unroll 1
            for (; i + 4 <= total; i += 4) {
                float4 q0 = satoms[i + 0], q1 = satoms[i + 1];
                float4 q2 = satoms[i + 2], q3 = satoms[i + 3];
                float dx0 = px - q0.x, dy0 = py - q0.y, dz0 = pz - q0.z;
                float dx1 = px - q1.x, dy1 = py - q1.y, dz1 = pz - q1.z;
                float dx2 = px - q2.x, dy2 = py - q2.y, dz2 = pz - q2.z;
                float dx3 = px - q3.x, dy3 = py - q3.y, dz3 = pz - q3.z;
                float d0 = fmaf(dx0, dx0, fmaf(dy0, dy0, dz0 * dz0));
                float d1 = fmaf(dx1, dx1, fmaf(dy1, dy1, dz1 * dz1));
                float d2 = fmaf(dx2, dx2, fmaf(dy2, dy2, dz2 * dz2));
                float d3 = fmaf(dx3, dx3, fmaf(dy3, dy3, dz3 * dz3));
                if (d0 < T) { if (cnt < BCAP) { fbuf[cnt] = d0; ibuf[cnt] = __float_as_int(q0.w); } ++cnt; }
                if (d1 < T) { if (cnt < BCAP) { fbuf[cnt] = d1; ibuf[cnt] = __float_as_int(q1.w); } ++cnt; }
                if (d2 < T) { if (cnt < BCAP) { fbuf[cnt] = d2; ibuf[cnt] = __float_as_int(q2.w); } ++cnt; }
                if (d3 < T) { if (cnt < BCAP) { fbuf[cnt] = d3; ibuf[cnt] = __float_as_int(q3.w); } ++cnt; }
            }
#pragma unroll 1
            for (; i < total; ++i) {
                float4 q = satoms[i];
                float dx = px - q.x, dy = py - q.y, dz = pz - q.z;
                float d = fmaf(dx, dx, fmaf(dy, dy, dz * dz));
                if (d < T) { if (cnt < BCAP) { fbuf[cnt] = d; ibuf[cnt] = __float_as_int(q.w); } ++cnt; }
            }

            const bool fb = active && (cnt < KNN || cnt > BCAP);

            // ---- phase 2: insertion only over buffered survivors ----
            if (active && !fb) {
#pragma unroll 1
                for (int j = 0; j < cnt; ++j) {
                    float d = fbuf[j];
                    if (d < worst) insert(d, ibuf[j]);
                }
            }

            // ---- rare exact fallback: full insert-scan of the staged set ----
            if (__any_sync(0xffffffffu, fb)) {
                if (fb) {
#pragma unroll 1
                    for (int j = 0; j < total; ++j) {
                        float4 q = satoms[j];
                        float dx = px - q.x, dy = py - q.y, dz = pz - q.z;
                        float d = fmaf(dx, dx, fmaf(dy, dy, dz * dz));
                        if (d < worst) insert(d, __float_as_int(q.w));
                    }
                }
            }
        } else if (active) {
            // staging overflow (essentially impossible): per-cell gmem insert scan
#pragma unroll 1
            for (int j = 0; j < 27; ++j) {
                const int na = s_cnt[j];
                const float4* __restrict__ ap = &g_atoms[s_gbase[j]];
#pragma unroll 1
                for (int i = 0; i < na; ++i) {
                    float4 q = ap[i];
                    float dx = px - q.x, dy = py - q.y, dz = pz - q.z;
                    float d = fmaf(dx, dx, fmaf(dy, dy, dz * dz));
                    if (d < worst) insert(d, __float_as_int(q.w));
                }
            }
        }

        // ---- guarantee check + rare shell expansion ----
        {
            int R = 1;
            while (true) {
                float g = INF;
                if (cx0 - R > 0)      g = fminf(g, px - (ox + (cx0 - R) * hx));
                if (cx0 + R < GS - 1) g = fminf(g, (ox + (cx0 + R + 1) * hx) - px);
                if (cy0 - R > 0)      g = fminf(g, py - (oy + (cy0 - R) * hy));
                if (cy0 + R < GS - 1) g = fminf(g, (oy + (cy0 + R + 1) * hy) - py);
                if (cz0 - R > 0)      g = fminf(g, pz - (oz + (cz0 - R) * hz));
                if (cz0 + R < GS - 1) g = fminf(g, (oz + (cz0 + R + 1) * hz) - pz);
                g = g - 1e-4f;
                if (worst <= g * g) break;
                ++R;
                const int zlo = max(cz0 - R, 0), zhi = min(cz0 + R, GS - 1);
                const int ylo = max(cy0 - R, 0), yhi = min(cy0 + R, GS - 1);
                const int xlo = max(cx0 - R, 0), xhi = min(cx0 + R, GS - 1);
                for (int cz = zlo; cz <= zhi; ++cz)
                    for (int cy = ylo; cy <= yhi; ++cy)
                        for (int cx = xlo; cx <= xhi; ++cx) {
                            int ch = max(abs(cx - cx0), max(abs(cy - cy0), abs(cz - cz0)));
                            if (ch != R) continue;
                            int c = (cz * GS + cy) * GS + cx;
                            float bx0 = ox + cx * hx, by0 = oy + cy * hy, bz0 = oz + cz * hz;
                            float tx = fmaxf(0.f, fmaxf(bx0 - px, px - (bx0 + hx)));
                            float ty = fmaxf(0.f, fmaxf(by0 - py, py - (by0 + hy)));
                            float tz = fmaxf(0.f, fmaxf(bz0 - pz, pz - (bz0 + hz)));
                            float mind = fmaf(tx, tx, fmaf(ty, ty, tz * tz));
                            if (mind < worst) {
                                int na = min(g_acnt[c], ACAP);
                                const float4* __restrict__ ap = &g_atoms[c * ACAP];
#pragma unroll 1
                                for (int i = 0; i < na; ++i) {
                                    float4 q = ap[i];
                                    float dx = px - q.x, dy = py - q.y, dz = pz - q.z;
                                    float d = fmaf(dx, dx, fmaf(dy, dy, dz * dz));
                                    if (d < worst) insert(d, __float_as_int(q.w));
                                }
                            }
                        }
            }
        }

        if (active) {
            float4* dp = reinterpret_cast<float4*>(g_ndist + (size_t)qi * KNN);
            int4*   ip = reinterpret_cast<int4*>(g_nidx + (size_t)qi * KNN);
            dp[0] = make_float4(dist[0],  dist[1],  dist[2],  dist[3]);
            dp[1] = make_float4(dist[4],  dist[5],  dist[6],  dist[7]);
            dp[2] = make_float4(dist[8],  dist[9],  dist[10], dist[11]);
            dp[3] = make_float4(dist[12], dist[13], dist[14], dist[15]);
            ip[0] = make_int4(idx[0],  idx[1],  idx[2],  idx[3]);
            ip[1] = make_int4(idx[4],  idx[5],  idx[6],  idx[7]);
            ip[2] = make_int4(idx[8],  idx[9],  idx[10], idx[11]);
            ip[3] = make_int4(idx[12], idx[13], idx[14], idx[15]);
        }
    }
}

// ---- MLP over the K neighbors ----
__global__ __launch_bounds__(128)
void k_mlp(const float* __restrict__ atype,
           const float* __restrict__ W1, const float* __restrict__ b1,
           const float* __restrict__ W2, const float* __restrict__ b2,
           const float* __restrict__ W3, const float* __restrict__ b3,
           const float* __restrict__ bn1g, const float* __restrict__ bn1b,
           const float* __restrict__ bn1m, const float* __restrict__ bn1v,
           const float* __restrict__ bn2g, const float* __restrict__ bn2b,
           const float* __restrict__ bn2m, const float* __restrict__ bn2v,
           float* __restrict__ out, int N)
{
    __shared__ float sW1[(D + 1) * D];
    __shared__ float sW2[D * D];
    __shared__ float sW3[2 * D * D];
    __shared__ float sb1[D], sb2[D], sb3[D];
    __shared__ float ss1[D], st1[D], ss2[D], st2[D];

    const int tid = threadIdx.x;
    for (int i = tid; i < (D + 1) * D; i += 128) sW1[i] = W1[i];
    for (int i = tid; i < D * D;       i += 128) sW2[i] = W2[i];
    for (int i = tid; i < 2 * D * D;   i += 128) sW3[i] = W3[i];
    if (tid < D) {
        sb1[tid] = b1[tid];
        sb2[tid] = b2[tid];
        sb3[tid] = b3[tid];
        float s1 = bn1g[tid] * rsqrtf(bn1v[tid] + 1e-5f);
        ss1[tid] = s1;
        st1[tid] = fmaf(-bn1m[tid], s1, bn1b[tid]);
        float s2 = bn2g[tid] * rsqrtf(bn2v[tid] + 1e-5f);
        ss2[tid] = s2;
        st2[tid] = fmaf(-bn2m[tid], s2, bn2b[tid]);
    }
    __syncthreads();

    const int n = blockIdx.x * 128 + tid;
    if (n >= N) return;

    const float4* dp = reinterpret_cast<const float4*>(g_ndist + (size_t)n * KNN);
    const int4*   ip = reinterpret_cast<const int4*>(g_nidx + (size_t)n * KNN);
    float4 dv[4] = {dp[0], dp[1], dp[2], dp[3]};
    int4   iv[4] = {ip[0], ip[1], ip[2], ip[3]};
    const float* dists = reinterpret_cast<const float*>(dv);
    const int*   idxs  = reinterpret_cast<const int*>(iv);

    float fx1[D], fx2[D];
#pragma unroll
    for (int d = 0; d < D; ++d) { fx1[d] = 0.f; fx2[d] = 0.f; }

#pragma unroll 1
    for (int k = 0; k < KNN; ++k) {
        const int   j  = idxs[k];
        const float dk = dists[k];

        const float4* ap = reinterpret_cast<const float4*>(atype + (size_t)j * D);
        float4 a0 = ap[0], a1 = ap[1], a2 = ap[2], a3 = ap[3];
        float f[D + 1] = {a0.x, a0.y, a0.z, a0.w,
                          a1.x, a1.y, a1.z, a1.w,
                          a2.x, a2.y, a2.z, a2.w,
                          a3.x, a3.y, a3.z, a3.w,
                          1.0f / dk};

        float h[D];
#pragma unroll
        for (int d = 0; d < D; ++d) h[d] = sb1[d];
#pragma unroll
        for (int s = 0; s < D + 1; ++s) {
            const float ft = f[s];
#pragma unroll
            for (int d = 0; d < D; ++d) h[d] = fmaf(ft, sW1[s * D + d], h[d]);
        }
#pragma unroll
        for (int d = 0; d < D; ++d) {
            float v = h[d];
            v = (v > 0.f) ? v : 0.2f * v;
            v = fmaf(v, ss1[d], st1[d]);
            h[d] = v;
            fx1[d] += v;
        }

        float h2[D];
#pragma unroll
        for (int d = 0; d < D; ++d) h2[d] = sb2[d];
#pragma unroll
        for (int s = 0; s < D; ++s) {
            const float ht = h[s];
#pragma unroll
            for (int d = 0; d < D; ++d) h2[d] = fmaf(ht, sW2[s * D + d], h2[d]);
        }
#pragma unroll
        for (int d = 0; d < D; ++d) {
            float v = h2[d];
            v = (v > 0.f) ? v : 0.2f * v;
            fx2[d] += fmaf(v, ss2[d], st2[d]);
        }
    }

    float o[D];
#pragma unroll
    for (int d = 0; d < D; ++d) o[d] = sb3[d];
#pragma unroll
    for (int s = 0; s < D; ++s) {
        const float a = fx1[s];
#pragma unroll
        for (int d = 0; d < D; ++d) o[d] = fmaf(a, sW3[s * D + d], o[d]);
    }
#pragma unroll
    for (int s = 0; s < D; ++s) {
        const float a = fx2[s];
#pragma unroll
        for (int d = 0; d < D; ++d) o[d] = fmaf(a, sW3[(D + s) * D + d], o[d]);
    }

    float4* op = reinterpret_cast<float4*>(out + (size_t)n * D);
    op[0] = make_float4(o[0],  o[1],  o[2],  o[3]);
    op[1] = make_float4(o[4],  o[5],  o[6],  o[7]);
    op[2] = make_float4(o[8],  o[9],  o[10], o[11]);
    op[3] = make_float4(o[12], o[13], o[14], o[15]);
}

__global__ void k_reset() {   // restore counters for the next graph replay
    int i = blockIdx.x * blockDim.x + threadIdx.x;
    if (i < NC) { g_acnt[i] = 0; g_qcnt[i] = 0; }
    if (i < 3)           g_bbenc[i] = 0x7fffffff;
    if (i >= 3 && i < 6) g_bbenc[i] = (int)0x80000000;
}

} // namespace

extern "C" void kernel_launch(void* const* d_in, const int* in_sizes, int n_in,
                              void* d_out, int out_size)
{
    const float* x     = (const float*)d_in[0];
    const float* y     = (const float*)d_in[1];
    const float* atype = (const float*)d_in[2];
    const float* W1    = (const float*)d_in[5];
    const float* b1    = (const float*)d_in[6];
    const float* W2    = (const float*)d_in[7];
    const float* b2    = (const float*)d_in[8];
    const float* W3    = (const float*)d_in[9];
    const float* b3    = (const float*)d_in[10];
    const float* bn1g  = (const float*)d_in[11];
    const float* bn1b  = (const float*)d_in[12];
    const float* bn1m  = (const float*)d_in[13];
    const float* bn1v  = (const float*)d_in[14];
    const float* bn2g  = (const float*)d_in[15];
    const float* bn2b  = (const float*)d_in[16];
    const float* bn2m  = (const float*)d_in[17];
    const float* bn2v  = (const float*)d_in[18];

    const int N = in_sizes[0] / 3;
    const int M = in_sizes[1] / 3;
    const int NM = (N > M) ? N : M;

    // k_knn is launch #4 — the one ncu captures
    k_bbox<<<(M + 255) / 256, 256>>>(y, M);
    k_params<<<1, 1>>>();
    k_bin<<<(NM + 255) / 256, 256>>>(x, y, N, M);
    k_knn<<<NC, KBLK>>>(x);
    k_mlp<<<(N + 127) / 128, 128>>>(atype,
                                    W1, b1, W2, b2, W3, b3,
                                    bn1g, bn1b, bn1m, bn1v,
                                    bn2g, bn2b, bn2m, bn2v,
                                    (float*)d_out, N);
    k_reset<<<(NC + 255) / 256, 256>>>();
}